// round 1
// baseline (speedup 1.0000x reference)
#include <cuda_runtime.h>
#include <cuda_bf16.h>
#include <cstdint>

// Problem dims (fixed by the dataset): x [4,2048,4096] -> M=8192, W [4096,4096]
#define M_TOTAL 8192
#define N_TOTAL 4096
#define K_TOTAL 4096

// Scratch for quantized operands (no cudaMalloc allowed)
__device__ int8_t g_xq[M_TOTAL * (size_t)K_TOTAL];   // 33.5 MB
__device__ int8_t g_wq[N_TOTAL * (size_t)K_TOTAL];   // 16.8 MB

// ---------------------------------------------------------------------------
// Quantize x: q = trunc(clip(x / input_scale, -128, 127)) -> int8
// Vectorized: float4 in, packed u32 (4x int8) out.
// ---------------------------------------------------------------------------
__global__ void quant_x_kernel(const float* __restrict__ x,
                               const float* __restrict__ iscale, int n4) {
    int i = blockIdx.x * blockDim.x + threadIdx.x;
    if (i >= n4) return;
    float s = *iscale;
    float4 v = reinterpret_cast<const float4*>(x)[i];
    int q0 = (int)fminf(fmaxf(__fdiv_rn(v.x, s), -128.f), 127.f);
    int q1 = (int)fminf(fmaxf(__fdiv_rn(v.y, s), -128.f), 127.f);
    int q2 = (int)fminf(fmaxf(__fdiv_rn(v.z, s), -128.f), 127.f);
    int q3 = (int)fminf(fmaxf(__fdiv_rn(v.w, s), -128.f), 127.f);
    uint32_t p = (uint32_t)(q0 & 0xFF) | ((uint32_t)(q1 & 0xFF) << 8) |
                 ((uint32_t)(q2 & 0xFF) << 16) | ((uint32_t)(q3 & 0xFF) << 24);
    reinterpret_cast<uint32_t*>(g_xq)[i] = p;
}

// quant_weight already holds exact int values in [-128,127] stored as fp32.
__global__ void quant_w_kernel(const float* __restrict__ w, int n4) {
    int i = blockIdx.x * blockDim.x + threadIdx.x;
    if (i >= n4) return;
    float4 v = reinterpret_cast<const float4*>(w)[i];
    int q0 = (int)v.x, q1 = (int)v.y, q2 = (int)v.z, q3 = (int)v.w;
    uint32_t p = (uint32_t)(q0 & 0xFF) | ((uint32_t)(q1 & 0xFF) << 8) |
                 ((uint32_t)(q2 & 0xFF) << 16) | ((uint32_t)(q3 & 0xFF) << 24);
    reinterpret_cast<uint32_t*>(g_wq)[i] = p;
}

// ---------------------------------------------------------------------------
// s8 GEMM: out[m][n] = (sum_k xq[m][k] * wq[n][k]) * (wscale[n]*iscale) + bias[n]
// Block tile 128x128x64, 8 warps (2x4), warp tile 64x32, mma.sync m16n8k32.s8,
// cp.async double-buffered shared tiles with 16B-pad rows (conflict-free frags).
// ---------------------------------------------------------------------------
#define BM 128
#define BN 128
#define BK 64
#define SROW 80   // 64 data bytes + 16 pad; multiple of 16 for cp.async

__device__ __forceinline__ void load_tile_async(int8_t* sm, const int8_t* g,
                                                int rowbase, int k0, int tid) {
#pragma unroll
    for (int j = 0; j < 2; ++j) {
        int e = tid + j * 256;          // 512 uint4 per 128x64 tile
        int row = e >> 2;
        int c16 = e & 3;
        uint32_t saddr = (uint32_t)__cvta_generic_to_shared(sm + row * SROW + c16 * 16);
        const int8_t* gp = g + (size_t)(rowbase + row) * K_TOTAL + k0 + c16 * 16;
        asm volatile("cp.async.cg.shared.global [%0], [%1], 16;\n"
                     :: "r"(saddr), "l"(gp));
    }
}

__global__ __launch_bounds__(256, 2) void gemm_s8_kernel(
    const float* __restrict__ wscale, const float* __restrict__ iscale,
    const float* __restrict__ bias, float* __restrict__ out) {
    __shared__ int8_t As[2][BM * SROW];
    __shared__ int8_t Bs[2][BN * SROW];

    const int tid = threadIdx.x;
    const int lane = tid & 31;
    const int warp = tid >> 5;
    const int warp_m = warp & 1;    // 2 warps along M (64 rows each)
    const int warp_n = warp >> 1;   // 4 warps along N (32 cols each)
    const int bm = blockIdx.y * BM;
    const int bn = blockIdx.x * BN;
    const int gr = lane >> 2;       // 0..7
    const int gc = lane & 3;        // 0..3

    int acc[4][4][4];
#pragma unroll
    for (int mi = 0; mi < 4; ++mi)
#pragma unroll
        for (int ni = 0; ni < 4; ++ni)
#pragma unroll
            for (int r = 0; r < 4; ++r) acc[mi][ni][r] = 0;

    const int KT = K_TOTAL / BK;    // 64 k-steps

    load_tile_async(As[0], g_xq, bm, 0, tid);
    load_tile_async(Bs[0], g_wq, bn, 0, tid);
    asm volatile("cp.async.commit_group;\n");

    for (int kt = 0; kt < KT; ++kt) {
        const int buf = kt & 1;
        if (kt + 1 < KT) {
            load_tile_async(As[buf ^ 1], g_xq, bm, (kt + 1) * BK, tid);
            load_tile_async(Bs[buf ^ 1], g_wq, bn, (kt + 1) * BK, tid);
            asm volatile("cp.async.commit_group;\n");
            asm volatile("cp.async.wait_group 1;\n");
        } else {
            asm volatile("cp.async.wait_group 0;\n");
        }
        __syncthreads();

#pragma unroll
        for (int kk = 0; kk < 2; ++kk) {     // two k=32 slices per BK=64
            uint32_t a[4][4];
            uint32_t b[4][2];
#pragma unroll
            for (int mi = 0; mi < 4; ++mi) {
                const int8_t* base = As[buf] +
                    (warp_m * 64 + mi * 16 + gr) * SROW + kk * 32 + gc * 4;
                a[mi][0] = *(const uint32_t*)(base);
                a[mi][1] = *(const uint32_t*)(base + 8 * SROW);
                a[mi][2] = *(const uint32_t*)(base + 16);
                a[mi][3] = *(const uint32_t*)(base + 8 * SROW + 16);
            }
#pragma unroll
            for (int ni = 0; ni < 4; ++ni) {
                const int8_t* base = Bs[buf] +
                    (warp_n * 32 + ni * 8 + gr) * SROW + kk * 32 + gc * 4;
                b[ni][0] = *(const uint32_t*)(base);
                b[ni][1] = *(const uint32_t*)(base + 16);
            }
#pragma unroll
            for (int mi = 0; mi < 4; ++mi)
#pragma unroll
                for (int ni = 0; ni < 4; ++ni) {
                    asm volatile(
                        "mma.sync.aligned.m16n8k32.row.col.s32.s8.s8.s32 "
                        "{%0,%1,%2,%3}, {%4,%5,%6,%7}, {%8,%9}, {%0,%1,%2,%3};\n"
                        : "+r"(acc[mi][ni][0]), "+r"(acc[mi][ni][1]),
                          "+r"(acc[mi][ni][2]), "+r"(acc[mi][ni][3])
                        : "r"(a[mi][0]), "r"(a[mi][1]), "r"(a[mi][2]), "r"(a[mi][3]),
                          "r"(b[ni][0]), "r"(b[ni][1]));
                }
        }
        __syncthreads();
    }

    // Epilogue: dequant + bias, float2 stores (d0,d1 are adjacent columns)
    const float is = *iscale;
#pragma unroll
    for (int mi = 0; mi < 4; ++mi) {
#pragma unroll
        for (int ni = 0; ni < 4; ++ni) {
            const int row = bm + warp_m * 64 + mi * 16 + gr;
            const int col = bn + warp_n * 32 + ni * 8 + gc * 2;
            const float s0 = wscale[col] * is;
            const float s1 = wscale[col + 1] * is;
            const float b0 = bias[col];
            const float b1 = bias[col + 1];
            float2 r0 = make_float2((float)acc[mi][ni][0] * s0 + b0,
                                    (float)acc[mi][ni][1] * s1 + b1);
            float2 r1 = make_float2((float)acc[mi][ni][2] * s0 + b0,
                                    (float)acc[mi][ni][3] * s1 + b1);
            *(float2*)(out + (size_t)row * N_TOTAL + col) = r0;
            *(float2*)(out + (size_t)(row + 8) * N_TOTAL + col) = r1;
        }
    }
}

// ---------------------------------------------------------------------------
// Inputs (metadata order): x, quant_weight, weight_scale, input_scale, bias
// ---------------------------------------------------------------------------
extern "C" void kernel_launch(void* const* d_in, const int* in_sizes, int n_in,
                              void* d_out, int out_size) {
    const float* x      = (const float*)d_in[0];
    const float* qw     = (const float*)d_in[1];
    const float* wscale = (const float*)d_in[2];
    const float* iscale = (const float*)d_in[3];
    const float* bias   = (const float*)d_in[4];
    float* out = (float*)d_out;

    {   // quantize x: 33,554,432 elems -> 8,388,608 float4
        int n4 = (M_TOTAL * K_TOTAL) / 4;
        quant_x_kernel<<<n4 / 256, 256>>>(x, iscale, n4);
    }
    {   // cast weights: 16,777,216 elems -> 4,194,304 float4
        int n4 = (N_TOTAL * K_TOTAL) / 4;
        quant_w_kernel<<<n4 / 256, 256>>>(qw, n4);
    }
    {
        dim3 grid(N_TOTAL / BN, M_TOTAL / BM);   // (32, 64)
        gemm_s8_kernel<<<grid, 256>>>(wscale, iscale, bias, out);
    }
}

// round 5
// speedup vs baseline: 1.0219x; 1.0219x over previous
#include <cuda_runtime.h>
#include <cstdint>

#define M_TOTAL 8192
#define N_TOTAL 4096
#define K_TOTAL 4096

// Scratch for quantized operands (no cudaMalloc allowed)
__device__ int8_t g_xq[(size_t)M_TOTAL * K_TOTAL];   // 33.5 MB
__device__ int8_t g_wq[(size_t)N_TOTAL * K_TOTAL];   // 16.8 MB

// ---------------------------------------------------------------------------
// Quantize x: q = trunc(clip(x / input_scale, -128, 127)) -> int8
// ---------------------------------------------------------------------------
__global__ void quant_x_kernel(const float* __restrict__ x,
                               const float* __restrict__ iscale, int n4) {
    int i = blockIdx.x * blockDim.x + threadIdx.x;
    if (i >= n4) return;
    float s = *iscale;
    float4 v = reinterpret_cast<const float4*>(x)[i];
    int q0 = (int)fminf(fmaxf(__fdiv_rn(v.x, s), -128.f), 127.f);
    int q1 = (int)fminf(fmaxf(__fdiv_rn(v.y, s), -128.f), 127.f);
    int q2 = (int)fminf(fmaxf(__fdiv_rn(v.z, s), -128.f), 127.f);
    int q3 = (int)fminf(fmaxf(__fdiv_rn(v.w, s), -128.f), 127.f);
    uint32_t p = (uint32_t)(q0 & 0xFF) | ((uint32_t)(q1 & 0xFF) << 8) |
                 ((uint32_t)(q2 & 0xFF) << 16) | ((uint32_t)(q3 & 0xFF) << 24);
    reinterpret_cast<uint32_t*>(g_xq)[i] = p;
}

__global__ void quant_w_kernel(const float* __restrict__ w, int n4) {
    int i = blockIdx.x * blockDim.x + threadIdx.x;
    if (i >= n4) return;
    float4 v = reinterpret_cast<const float4*>(w)[i];
    int q0 = (int)v.x, q1 = (int)v.y, q2 = (int)v.z, q3 = (int)v.w;
    uint32_t p = (uint32_t)(q0 & 0xFF) | ((uint32_t)(q1 & 0xFF) << 8) |
                 ((uint32_t)(q2 & 0xFF) << 16) | ((uint32_t)(q3 & 0xFF) << 24);
    reinterpret_cast<uint32_t*>(g_wq)[i] = p;
}

// ---------------------------------------------------------------------------
// s8 GEMM via mma.sync (tcgen05 unavailable: harness PTX target is sm_103,
// not sm_103a). Block tile 128x128x128, 3-stage cp.async, SW128 swizzle,
// ldmatrix.x4 fragment loads, warp tile 64x32.
// ---------------------------------------------------------------------------
#define BM 128
#define BN 128
#define BK 128
#define KT (K_TOTAL / BK)          // 32
#define STAGES 3
#define A_TILE (BM * BK)           // 16384 B
#define B_TILE (BN * BK)           // 16384 B
#define STAGE_BYTES (A_TILE + B_TILE)          // 32768
#define SMEM_TOTAL (STAGES * STAGE_BYTES)      // 98304

static __device__ __forceinline__ uint32_t smem_u32(const void* p) {
    uint32_t a;
    asm("{ .reg .u64 t; cvta.to.shared.u64 t, %1; cvt.u32.u64 %0, t; }"
        : "=r"(a) : "l"(p));
    return a;
}
static __device__ __forceinline__ uint32_t sw128(uint32_t o) {
    return o ^ ((o >> 3) & 0x70);
}
static __device__ __forceinline__ void cp16(uint32_t saddr, const void* g) {
    asm volatile("cp.async.cg.shared.global [%0], [%1], 16;\n" :: "r"(saddr), "l"(g));
}
static __device__ __forceinline__ void ldsm4(uint32_t& r0, uint32_t& r1,
                                             uint32_t& r2, uint32_t& r3,
                                             uint32_t addr) {
    asm volatile("ldmatrix.sync.aligned.m8n8.x4.shared.b16 {%0,%1,%2,%3}, [%4];"
                 : "=r"(r0), "=r"(r1), "=r"(r2), "=r"(r3) : "r"(addr));
}

// cp.async a 128x128 A tile + 128x128 B tile into SW128-swizzled smem stage
static __device__ __forceinline__ void load_stage(uint32_t s_u, int chunk,
                                                  int bm, int bn, int tid) {
    const int k0 = chunk * BK;
    const uint32_t sb_u = s_u + A_TILE;
#pragma unroll
    for (int i = 0; i < 4; ++i) {               // A: 1024 x 16B
        int e = i * 256 + tid;
        int row = e >> 3, c16 = (e & 7) * 16;
        cp16(s_u + sw128(row * BK + c16),
             g_xq + (size_t)(bm + row) * K_TOTAL + k0 + c16);
    }
#pragma unroll
    for (int i = 0; i < 4; ++i) {               // B: 1024 x 16B
        int e = i * 256 + tid;
        int row = e >> 3, c16 = (e & 7) * 16;
        cp16(sb_u + sw128(row * BK + c16),
             g_wq + (size_t)(bn + row) * K_TOTAL + k0 + c16);
    }
}

__global__ __launch_bounds__(256, 2) void gemm_s8_kernel(
    const float* __restrict__ wscale, const float* __restrict__ iscale,
    const float* __restrict__ bias, float* __restrict__ out) {
    extern __shared__ char smem[];
    const uint32_t smem_base = smem_u32(smem);

    const int tid = threadIdx.x;
    const int lane = tid & 31;
    const int warp = tid >> 5;
    const int warp_m = warp & 1;    // 2 warps along M (64 rows each)
    const int warp_n = warp >> 1;   // 4 warps along N (32 cols each)
    const int bm = blockIdx.y * BM;
    const int bn = blockIdx.x * BN;

    // ldmatrix per-thread row mapping: grp 0..3 -> (rows 0-7, k+0), (rows 8-15, k+0),
    // (rows 0-7, k+16), (rows 8-15, k+16)
    const int grp = lane >> 3, r8 = lane & 7;
    const int lrow = (grp & 1) * 8 + r8;        // row within 16-row matrix tile
    const int lcol = (grp >> 1) * 16;           // 0 or 16 bytes within k-slice

    int acc[4][4][4];
#pragma unroll
    for (int mi = 0; mi < 4; ++mi)
#pragma unroll
        for (int ni = 0; ni < 4; ++ni)
#pragma unroll
            for (int r = 0; r < 4; ++r) acc[mi][ni][r] = 0;

    // Prologue: chunks 0 and 1
    load_stage(smem_base, 0, bm, bn, tid);
    asm volatile("cp.async.commit_group;\n");
    load_stage(smem_base + STAGE_BYTES, 1, bm, bn, tid);
    asm volatile("cp.async.commit_group;\n");

    uint32_t stage_u = smem_base;               // stage for compute at kt
    uint32_t pf_u = smem_base + 2 * STAGE_BYTES;

    for (int kt = 0; kt < KT; ++kt) {
        if (kt + 2 < KT) load_stage(pf_u, kt + 2, bm, bn, tid);
        asm volatile("cp.async.commit_group;\n");
        asm volatile("cp.async.wait_group 2;\n");   // chunk kt resident
        __syncthreads();

        const uint32_t sA = stage_u;
        const uint32_t sB = stage_u + A_TILE;
#pragma unroll
        for (int kk = 0; kk < 4; ++kk) {            // 4 x K=32 slices
            const int kcol = kk * 32 + lcol;
            uint32_t a[4][4];
#pragma unroll
            for (int mi = 0; mi < 4; ++mi) {
                uint32_t addr = sA + sw128(
                    (uint32_t)(warp_m * 64 + mi * 16 + lrow) * BK + kcol);
                ldsm4(a[mi][0], a[mi][1], a[mi][2], a[mi][3], addr);
            }
            uint32_t b[4][2];
#pragma unroll
            for (int np = 0; np < 2; ++np) {        // 16 n-rows per LDSM
                uint32_t addr = sB + sw128(
                    (uint32_t)(warp_n * 32 + np * 16 + lrow) * BK + kcol);
                uint32_t m0, m1, m2, m3;
                ldsm4(m0, m1, m2, m3, addr);
                b[2 * np][0] = m0; b[2 * np + 1][0] = m1;
                b[2 * np][1] = m2; b[2 * np + 1][1] = m3;
            }
#pragma unroll
            for (int mi = 0; mi < 4; ++mi)
#pragma unroll
                for (int ni = 0; ni < 4; ++ni) {
                    asm volatile(
                        "mma.sync.aligned.m16n8k32.row.col.s32.s8.s8.s32 "
                        "{%0,%1,%2,%3}, {%4,%5,%6,%7}, {%8,%9}, {%0,%1,%2,%3};\n"
                        : "+r"(acc[mi][ni][0]), "+r"(acc[mi][ni][1]),
                          "+r"(acc[mi][ni][2]), "+r"(acc[mi][ni][3])
                        : "r"(a[mi][0]), "r"(a[mi][1]), "r"(a[mi][2]), "r"(a[mi][3]),
                          "r"(b[ni][0]), "r"(b[ni][1]));
                }
        }
        __syncthreads();                            // stage free for prefetch reuse
        uint32_t t = stage_u;                       // rotate ring
        stage_u = (stage_u == smem_base + 2 * STAGE_BYTES) ? smem_base
                                                           : stage_u + STAGE_BYTES;
        pf_u = t;
    }

    // Epilogue: dequant + bias, float2 stores (d0,d1 are adjacent columns)
    const float is = *iscale;
    const int gr = lane >> 2, gc = lane & 3;
#pragma unroll
    for (int mi = 0; mi < 4; ++mi) {
#pragma unroll
        for (int ni = 0; ni < 4; ++ni) {
            const int row = bm + warp_m * 64 + mi * 16 + gr;
            const int col = bn + warp_n * 32 + ni * 8 + gc * 2;
            const float s0 = wscale[col] * is;
            const float s1 = wscale[col + 1] * is;
            const float b0 = bias[col];
            const float b1 = bias[col + 1];
            float2 r0 = make_float2((float)acc[mi][ni][0] * s0 + b0,
                                    (float)acc[mi][ni][1] * s1 + b1);
            float2 r1 = make_float2((float)acc[mi][ni][2] * s0 + b0,
                                    (float)acc[mi][ni][3] * s1 + b1);
            *(float2*)(out + (size_t)row * N_TOTAL + col) = r0;
            *(float2*)(out + (size_t)(row + 8) * N_TOTAL + col) = r1;
        }
    }
}

// ---------------------------------------------------------------------------
// Inputs (metadata order): x, quant_weight, weight_scale, input_scale, bias
// ---------------------------------------------------------------------------
extern "C" void kernel_launch(void* const* d_in, const int* in_sizes, int n_in,
                              void* d_out, int out_size) {
    const float* x      = (const float*)d_in[0];
    const float* qw     = (const float*)d_in[1];
    const float* wscale = (const float*)d_in[2];
    const float* iscale = (const float*)d_in[3];
    const float* bias   = (const float*)d_in[4];
    float* out = (float*)d_out;

    cudaFuncSetAttribute(gemm_s8_kernel,
                         cudaFuncAttributeMaxDynamicSharedMemorySize, SMEM_TOTAL);

    {   // quantize x
        int n4 = (M_TOTAL * K_TOTAL) / 4;
        quant_x_kernel<<<n4 / 256, 256>>>(x, iscale, n4);
    }
    {   // cast weights
        int n4 = (N_TOTAL * K_TOTAL) / 4;
        quant_w_kernel<<<n4 / 256, 256>>>(qw, n4);
    }
    {
        dim3 grid(N_TOTAL / BN, M_TOTAL / BM);  // (32, 64) = 2048 CTAs
        gemm_s8_kernel<<<grid, 256, SMEM_TOTAL>>>(wscale, iscale, bias, out);
    }
}

// round 7
// speedup vs baseline: 2.4370x; 2.3848x over previous
#include <cuda_runtime.h>
#include <cuda_bf16.h>
#include <cstdint>

#define M_TOTAL 8192
#define N_TOTAL 4096
#define K_TOTAL 4096

// Quantized operands held as bf16 (int values in [-128,127] are EXACT in bf16)
__device__ __nv_bfloat16 g_xq[(size_t)M_TOTAL * K_TOTAL];   // 67 MB
__device__ __nv_bfloat16 g_wq[(size_t)N_TOTAL * K_TOTAL];   // 33.5 MB

// ---------------------------------------------------------------------------
// Quantize x: q = trunc(clip(x / input_scale, -128, 127)) -> bf16(int)
// ---------------------------------------------------------------------------
__global__ void quant_x_kernel(const float* __restrict__ x,
                               const float* __restrict__ iscale, int n4) {
    int i = blockIdx.x * blockDim.x + threadIdx.x;
    if (i >= n4) return;
    float s = *iscale;
    float4 v = reinterpret_cast<const float4*>(x)[i];
    float q0 = truncf(fminf(fmaxf(__fdiv_rn(v.x, s), -128.f), 127.f));
    float q1 = truncf(fminf(fmaxf(__fdiv_rn(v.y, s), -128.f), 127.f));
    float q2 = truncf(fminf(fmaxf(__fdiv_rn(v.z, s), -128.f), 127.f));
    float q3 = truncf(fminf(fmaxf(__fdiv_rn(v.w, s), -128.f), 127.f));
    __nv_bfloat162 p0 = __floats2bfloat162_rn(q0, q1);
    __nv_bfloat162 p1 = __floats2bfloat162_rn(q2, q3);
    uint2 p = make_uint2(*(uint32_t*)&p0, *(uint32_t*)&p1);
    reinterpret_cast<uint2*>(g_xq)[i] = p;
}

// quant_weight already holds exact small ints stored as fp32 -> bf16 exact
__global__ void quant_w_kernel(const float* __restrict__ w, int n4) {
    int i = blockIdx.x * blockDim.x + threadIdx.x;
    if (i >= n4) return;
    float4 v = reinterpret_cast<const float4*>(w)[i];
    __nv_bfloat162 p0 = __floats2bfloat162_rn(v.x, v.y);
    __nv_bfloat162 p1 = __floats2bfloat162_rn(v.z, v.w);
    uint2 p = make_uint2(*(uint32_t*)&p0, *(uint32_t*)&p1);
    reinterpret_cast<uint2*>(g_wq)[i] = p;
}

// ---------------------------------------------------------------------------
// bf16 GEMM via mma.sync.m16n8k16.f32.bf16.bf16.f32.
// Block tile 128x128 x BK=64 elems (=128B rows, SW128), 3-stage cp.async,
// ldmatrix.x4 fragments, warp tile 64x32, fp32 accumulators.
// ---------------------------------------------------------------------------
#define BM 128
#define BN 128
#define BKE 64                      // K elements per chunk
#define BKB 128                     // K bytes per row (bf16)
#define KT (K_TOTAL / BKE)          // 64
#define A_TILE (BM * BKB)           // 16384 B
#define B_TILE (BN * BKB)           // 16384 B
#define STAGE_BYTES (A_TILE + B_TILE)          // 32768
#define SMEM_TOTAL (3 * STAGE_BYTES)           // 98304

static __device__ __forceinline__ uint32_t smem_u32(const void* p) {
    uint32_t a;
    asm("{ .reg .u64 t; cvta.to.shared.u64 t, %1; cvt.u32.u64 %0, t; }"
        : "=r"(a) : "l"(p));
    return a;
}
static __device__ __forceinline__ uint32_t sw128(uint32_t o) {
    return o ^ ((o >> 3) & 0x70);
}
static __device__ __forceinline__ void cp16(uint32_t saddr, const void* g) {
    asm volatile("cp.async.cg.shared.global [%0], [%1], 16;\n" :: "r"(saddr), "l"(g));
}
static __device__ __forceinline__ void ldsm4(uint32_t& r0, uint32_t& r1,
                                             uint32_t& r2, uint32_t& r3,
                                             uint32_t addr) {
    asm volatile("ldmatrix.sync.aligned.m8n8.x4.shared.b16 {%0,%1,%2,%3}, [%4];"
                 : "=r"(r0), "=r"(r1), "=r"(r2), "=r"(r3) : "r"(addr));
}

// cp.async a 128x64 A tile + 128x64 B tile (bf16) into SW128 smem stage
static __device__ __forceinline__ void load_stage(uint32_t s_u, int chunk,
                                                  int bm, int bn, int tid) {
    const int k0 = chunk * BKE;
    const uint32_t sb_u = s_u + A_TILE;
#pragma unroll
    for (int i = 0; i < 4; ++i) {               // A: 1024 x 16B
        int e = i * 256 + tid;
        int row = e >> 3, c16 = (e & 7) * 16;   // byte col within 128B row
        cp16(s_u + sw128(row * BKB + c16),
             g_xq + (size_t)(bm + row) * K_TOTAL + k0 + c16 / 2);
    }
#pragma unroll
    for (int i = 0; i < 4; ++i) {               // B: 1024 x 16B
        int e = i * 256 + tid;
        int row = e >> 3, c16 = (e & 7) * 16;
        cp16(sb_u + sw128(row * BKB + c16),
             g_wq + (size_t)(bn + row) * K_TOTAL + k0 + c16 / 2);
    }
}

__global__ __launch_bounds__(256, 2) void gemm_bf16_kernel(
    const float* __restrict__ wscale, const float* __restrict__ iscale,
    const float* __restrict__ bias, float* __restrict__ out) {
    extern __shared__ char smem[];
    const uint32_t smem_base = smem_u32(smem);

    const int tid = threadIdx.x;
    const int lane = tid & 31;
    const int warp = tid >> 5;
    const int warp_m = warp & 1;    // 2 warps along M (64 rows each)
    const int warp_n = warp >> 1;   // 4 warps along N (32 cols each)
    const int bm = blockIdx.y * BM;
    const int bn = blockIdx.x * BN;

    // ldmatrix lane mapping: grp 0..3 -> (rows 0-7,+0B) (rows 8-15,+0B)
    // (rows 0-7,+16B) (rows 8-15,+16B)
    const int grp = lane >> 3, r8 = lane & 7;
    const int lrow = (grp & 1) * 8 + r8;
    const int lcol = (grp >> 1) * 16;           // byte offset within 32B k-slice

    float acc[4][4][4];
#pragma unroll
    for (int mi = 0; mi < 4; ++mi)
#pragma unroll
        for (int ni = 0; ni < 4; ++ni)
#pragma unroll
            for (int r = 0; r < 4; ++r) acc[mi][ni][r] = 0.f;

    // Prologue: chunks 0 and 1
    load_stage(smem_base, 0, bm, bn, tid);
    asm volatile("cp.async.commit_group;\n");
    load_stage(smem_base + STAGE_BYTES, 1, bm, bn, tid);
    asm volatile("cp.async.commit_group;\n");

    uint32_t stage_u = smem_base;
    uint32_t pf_u = smem_base + 2 * STAGE_BYTES;

    for (int kt = 0; kt < KT; ++kt) {
        if (kt + 2 < KT) load_stage(pf_u, kt + 2, bm, bn, tid);
        asm volatile("cp.async.commit_group;\n");
        asm volatile("cp.async.wait_group 2;\n");
        __syncthreads();

        const uint32_t sA = stage_u;
        const uint32_t sB = stage_u + A_TILE;
#pragma unroll
        for (int kk = 0; kk < 4; ++kk) {        // 4 x k16 slices (32B each)
            const int kcol = kk * 32 + lcol;
            uint32_t a[4][4];
#pragma unroll
            for (int mi = 0; mi < 4; ++mi) {
                uint32_t addr = sA + sw128(
                    (uint32_t)(warp_m * 64 + mi * 16 + lrow) * BKB + kcol);
                ldsm4(a[mi][0], a[mi][1], a[mi][2], a[mi][3], addr);
            }
            uint32_t b[4][2];
#pragma unroll
            for (int np = 0; np < 2; ++np) {    // 16 n-rows per LDSM
                uint32_t addr = sB + sw128(
                    (uint32_t)(warp_n * 32 + np * 16 + lrow) * BKB + kcol);
                uint32_t m0, m1, m2, m3;
                ldsm4(m0, m1, m2, m3, addr);
                b[2 * np][0] = m0; b[2 * np + 1][0] = m1;
                b[2 * np][1] = m2; b[2 * np + 1][1] = m3;
            }
#pragma unroll
            for (int mi = 0; mi < 4; ++mi)
#pragma unroll
                for (int ni = 0; ni < 4; ++ni) {
                    asm volatile(
                        "mma.sync.aligned.m16n8k16.row.col.f32.bf16.bf16.f32 "
                        "{%0,%1,%2,%3}, {%4,%5,%6,%7}, {%8,%9}, {%0,%1,%2,%3};\n"
                        : "+f"(acc[mi][ni][0]), "+f"(acc[mi][ni][1]),
                          "+f"(acc[mi][ni][2]), "+f"(acc[mi][ni][3])
                        : "r"(a[mi][0]), "r"(a[mi][1]), "r"(a[mi][2]), "r"(a[mi][3]),
                          "r"(b[ni][0]), "r"(b[ni][1]));
                }
        }
        __syncthreads();
        uint32_t t = stage_u;
        stage_u = (stage_u == smem_base + 2 * STAGE_BYTES) ? smem_base
                                                           : stage_u + STAGE_BYTES;
        pf_u = t;
    }

    // Epilogue: dequant + bias (acc already fp32, exact integer values)
    const float is = *iscale;
    const int gr = lane >> 2, gc = lane & 3;
#pragma unroll
    for (int mi = 0; mi < 4; ++mi) {
#pragma unroll
        for (int ni = 0; ni < 4; ++ni) {
            const int row = bm + warp_m * 64 + mi * 16 + gr;
            const int col = bn + warp_n * 32 + ni * 8 + gc * 2;
            const float s0 = wscale[col] * is;
            const float s1 = wscale[col + 1] * is;
            const float b0 = bias[col];
            const float b1 = bias[col + 1];
            float2 r0 = make_float2(fmaf(acc[mi][ni][0], s0, b0),
                                    fmaf(acc[mi][ni][1], s1, b1));
            float2 r1 = make_float2(fmaf(acc[mi][ni][2], s0, b0),
                                    fmaf(acc[mi][ni][3], s1, b1));
            *(float2*)(out + (size_t)row * N_TOTAL + col) = r0;
            *(float2*)(out + (size_t)(row + 8) * N_TOTAL + col) = r1;
        }
    }
}

// ---------------------------------------------------------------------------
// Inputs (metadata order): x, quant_weight, weight_scale, input_scale, bias
// ---------------------------------------------------------------------------
extern "C" void kernel_launch(void* const* d_in, const int* in_sizes, int n_in,
                              void* d_out, int out_size) {
    const float* x      = (const float*)d_in[0];
    const float* qw     = (const float*)d_in[1];
    const float* wscale = (const float*)d_in[2];
    const float* iscale = (const float*)d_in[3];
    const float* bias   = (const float*)d_in[4];
    float* out = (float*)d_out;

    cudaFuncSetAttribute(gemm_bf16_kernel,
                         cudaFuncAttributeMaxDynamicSharedMemorySize, SMEM_TOTAL);

    {   // quantize x -> bf16 ints
        int n4 = (M_TOTAL * K_TOTAL) / 4;
        quant_x_kernel<<<n4 / 256, 256>>>(x, iscale, n4);
    }
    {   // cast weights -> bf16 ints
        int n4 = (N_TOTAL * K_TOTAL) / 4;
        quant_w_kernel<<<n4 / 256, 256>>>(qw, n4);
    }
    {
        dim3 grid(N_TOTAL / BN, M_TOTAL / BM);  // (32, 64) = 2048 CTAs
        gemm_bf16_kernel<<<grid, 256, SMEM_TOTAL>>>(wscale, iscale, bias, out);
    }
}